// round 1
// baseline (speedup 1.0000x reference)
#include <cuda_runtime.h>
#include <cstdint>

// Problem shape (fixed by the dataset)
#define BB 4
#define NN 65536
#define NHH 7
#define EE 128

static const long long ROWS      = (long long)BB * NN * NHH;   // 1,835,008 gather rows
static const long long XNH_ELEMS = ROWS * EE;                  // 234,881,024 floats

// One warp per (b, n, h) row. 32 lanes x float4 = 128 floats = 512B
// coalesced read from the gathered x row and 512B coalesced write.
// Output stores use streaming hint (__stcs) so the 939MB output stream
// doesn't evict the per-batch 33.5MB x slice we want resident in L2.
__global__ void __launch_bounds__(256) gather_x_kernel(
    const float4* __restrict__ x,          // [B*N*32] float4  (B,N,1,128 fp32)
    const int*    __restrict__ adjc,       // [N*NH]
    const int*    __restrict__ lidx,       // [B*N]
    const int*    __restrict__ bsi,        // [B]
    const int*    __restrict__ slevel,     // [1] or null
    float4*       __restrict__ out)        // [ROWS*32] float4
{
    long long tid = (long long)blockIdx.x * blockDim.x + threadIdx.x;
    long long row = tid >> 5;
    int lane = (int)(tid & 31);
    if (row >= ROWS) return;

    int h        = (int)(row % NHH);
    long long bn = row / NHH;
    int n        = (int)(bn % NN);
    int b        = (int)(bn / NN);

    int li  = __ldg(&lidx[b * NN + n]);
    int lvl = (slevel != nullptr) ? __ldg(&slevel[0]) : 0;
    int off = __ldg(&bsi[b]) << (2 * lvl);      // bsi * 4^lvl
    int idx = __ldg(&adjc[li * NHH + h]) - off;

    float4 v = __ldg(&x[((long long)b * NN + idx) * 32 + lane]);
    __stcs(&out[row * 32 + lane], v);
}

// Mask: out_mask[b,n,h] = adjc_mask_invalid[local_indices[b,n], h] as float 0/1.
__global__ void __launch_bounds__(256) mask_kernel(
    const unsigned char* __restrict__ mi,   // [N*NH] bool bytes
    const int*           __restrict__ lidx, // [B*N]
    float*               __restrict__ out,  // [count]
    long long count)
{
    long long i = (long long)blockIdx.x * blockDim.x + threadIdx.x;
    if (i >= count) return;
    int h        = (int)(i % NHH);
    long long bn = i / NHH;
    int n        = (int)(bn % NN);
    int b        = (int)(bn / NN);
    int li = __ldg(&lidx[b * NN + n]);
    out[i] = __ldg(&mi[li * NHH + h]) ? 1.0f : 0.0f;
}

extern "C" void kernel_launch(void* const* d_in, const int* in_sizes, int n_in,
                              void* d_out, int out_size)
{
    const float4*        x    = (const float4*)d_in[0];
    const int*           adjc = (const int*)d_in[1];
    const unsigned char* mi   = (const unsigned char*)d_in[2];
    const int*           lidx = (const int*)d_in[3];
    const int*           bsi  = (const int*)d_in[4];
    const int*           slv  = (n_in >= 6) ? (const int*)d_in[5] : nullptr;

    float* out = (float*)d_out;

    // x_nh gather: ROWS*32 float4 slots, one lane each
    {
        long long threads_total = ROWS * 32;
        int  tpb    = 256;
        long long blocks = (threads_total + tpb - 1) / tpb;
        gather_x_kernel<<<(unsigned int)blocks, tpb>>>(
            x, adjc, lidx, bsi, slv, (float4*)out);
    }

    // Mask tail (if the output buffer includes it)
    long long mask_count = (long long)out_size - XNH_ELEMS;
    if (mask_count > 0) {
        int tpb = 256;
        long long blocks = (mask_count + tpb - 1) / tpb;
        mask_kernel<<<(unsigned int)blocks, tpb>>>(
            mi, lidx, out + XNH_ELEMS, mask_count);
    }
}

// round 3
// speedup vs baseline: 1.7253x; 1.7253x over previous
#include <cuda_runtime.h>
#include <cstdint>

// Problem shape (fixed by the dataset)
#define BB 4
#define NN 65536
#define NHH 7
#define EE 128

static const long long PAIRS     = (long long)BB * NN;          // 262,144 (b,n) pairs
static const long long ROWS      = PAIRS * NHH;                 // 1,835,008 gather rows
static const long long XNH_ELEMS = ROWS * EE;                   // 234,881,024 floats

// One warp per (b,n): gathers all 7 neighbor rows (7 independent LDG.128 per
// lane -> MLP=7), streams them out with __stcs (don't pollute L2 with the
// 939MB output stream), and lanes 0..6 emit the mask floats.
__global__ void __launch_bounds__(256) gather_nh_kernel(
    const float4*        __restrict__ x,     // [B*N*32] float4 (B,N,1,128 fp32)
    const int*           __restrict__ adjc,  // [N*NH]
    const unsigned char* __restrict__ mi,    // [N*NH] bool bytes
    const int*           __restrict__ lidx,  // [B*N]
    const int*           __restrict__ bsi,   // [B]
    const int*           __restrict__ slevel,// [1] or null
    float4*              __restrict__ out,   // [ROWS*32] float4
    float*               __restrict__ mout)  // [ROWS] or null
{
    long long tid = (long long)blockIdx.x * blockDim.x + threadIdx.x;
    long long w   = tid >> 5;                 // (b,n) pair index
    int lane = (int)(tid & 31);
    if (w >= PAIRS) return;

    int b = (int)(w / NN);
    int n = (int)(w % NN);

    int li  = __ldg(&lidx[b * NN + n]);
    int lvl = (slevel != nullptr) ? __ldg(&slevel[0]) : 0;
    int off = __ldg(&bsi[b]) << (2 * lvl);    // bsi * 4^lvl

    int idx[NHH];
    #pragma unroll
    for (int h = 0; h < NHH; h++)
        idx[h] = __ldg(&adjc[li * NHH + h]) - off;

    const float4* xb = x + (long long)b * NN * 32;

    float4 v[NHH];
    #pragma unroll
    for (int h = 0; h < NHH; h++)             // 7 independent 512B gather reads
        v[h] = __ldg(&xb[(long long)idx[h] * 32 + lane]);

    float4* o = out + w * NHH * 32;
    #pragma unroll
    for (int h = 0; h < NHH; h++)
        __stcs(&o[h * 32 + lane], v[h]);

    if (mout != nullptr && lane < NHH)
        mout[w * NHH + lane] = __ldg(&mi[li * NHH + lane]) ? 1.0f : 0.0f;
}

extern "C" void kernel_launch(void* const* d_in, const int* in_sizes, int n_in,
                              void* d_out, int out_size)
{
    const float4*        x    = (const float4*)d_in[0];
    const int*           adjc = (const int*)d_in[1];
    const unsigned char* mi   = (const unsigned char*)d_in[2];
    const int*           lidx = (const int*)d_in[3];
    const int*           bsi  = (const int*)d_in[4];
    const int*           slv  = (n_in >= 6) ? (const int*)d_in[5] : nullptr;

    float* out = (float*)d_out;
    float* mout = ((long long)out_size > XNH_ELEMS) ? out + XNH_ELEMS : nullptr;

    long long threads_total = PAIRS * 32;     // one warp per (b,n)
    int tpb = 256;
    long long blocks = (threads_total + tpb - 1) / tpb;
    gather_nh_kernel<<<(unsigned int)blocks, tpb>>>(
        x, adjc, mi, lidx, bsi, slv, (float4*)out, mout);
}